// round 1
// baseline (speedup 1.0000x reference)
#include <cuda_runtime.h>

#define T_STEPS 2048
#define BATCH   256
#define HID     128
#define G3      384      // 3*H gate rows
#define NROWS   385      // 384 Whh rows + 1 Wfc row
#define RPAD    132      // padded row length (floats); 132*4B=528B=33*16B -> conflict-free LDS.128
#define NTHREADS 416     // 13 warps; threads 0..384 = dot rows, warp 12 lanes also do prefetch
#define GH_STRIDE 400    // padded ghs row stride

__global__ void __launch_bounds__(NTHREADS, 1)
gru_impute_kernel(const float* __restrict__ x,     // [B, T] (I=1)
                  const float* __restrict__ Wih,   // [384, 1]
                  const float* __restrict__ Whh,   // [384, 128]
                  const float* __restrict__ bih,   // [384]
                  const float* __restrict__ bhh,   // [384]
                  const float* __restrict__ Wfc,   // [1, 128]
                  const float* __restrict__ bfc,   // [1]
                  float* __restrict__ out)
{
    extern __shared__ float sm[];
    float* ws   = sm;                      // NROWS * RPAD   (Whh rows + Wfc as row 384)
    float* ghs  = ws   + NROWS * RPAD;     // 2 * GH_STRIDE  (gate pre-acts per batch)
    float* hs   = ghs  + 2 * GH_STRIDE;    // 2 * HID        (hidden state per batch)
    float* wihs = hs   + 2 * HID;          // 384
    float* bihs = wihs + G3;               // 384
    float* xts  = bihs + G3;               // 2 buffers * 2 batches

    const int tid = threadIdx.x;
    const int b0  = blockIdx.x * 2;        // this CTA owns batches b0, b0+1

    // ---- one-time staging: weights into smem, h=0, first x values ----
    for (int idx = tid; idx < NROWS * HID; idx += NTHREADS) {
        int r = idx >> 7, c = idx & 127;
        ws[r * RPAD + c] = (r < G3) ? Whh[r * HID + c] : Wfc[c];
    }
    for (int idx = tid; idx < G3; idx += NTHREADS) {
        wihs[idx] = Wih[idx];
        bihs[idx] = bih[idx];
    }
    for (int idx = tid; idx < 2 * HID; idx += NTHREADS) hs[idx] = 0.0f;
    if (tid < 2) xts[tid] = x[(b0 + tid) * T_STEPS + 0];   // buffer 0 = step 0

    float breg = 0.0f;                     // per-row bias held in register
    if (tid < G3)       breg = bhh[tid];
    else if (tid == G3) breg = bfc[0];
    __syncthreads();

    float* newin = out;                          // [T, B] row-major
    float* pred  = out + T_STEPS * BATCH;        // [B, T-1] row-major

    for (int t = 0; t < T_STEPS; ++t) {
        // prefetch x[t+1] (threads 408/409 are idle in phase A; LDG hidden under matvec)
        float xn = 0.0f;
        const bool pf = (tid >= 408) && (tid < 410) && (t + 1 < T_STEPS);
        if (pf) xn = x[(b0 + (tid - 408)) * T_STEPS + (t + 1)];

        // ---- Phase A: gh[j][b] = dot(h[b], row_j) + bias  (row 384 = x_hat) ----
        if (tid < NROWS) {
            const float4* wrow = reinterpret_cast<const float4*>(ws + tid * RPAD);
            const float4* h0   = reinterpret_cast<const float4*>(hs);
            const float4* h1   = reinterpret_cast<const float4*>(hs + HID);
            float a0 = 0.f, a1 = 0.f, a2 = 0.f, a3 = 0.f;
            float c0 = 0.f, c1 = 0.f, c2 = 0.f, c3 = 0.f;
            #pragma unroll
            for (int k = 0; k < HID / 4; ++k) {
                float4 w = wrow[k];
                float4 p = h0[k];
                float4 q = h1[k];
                a0 = fmaf(w.x, p.x, a0); a1 = fmaf(w.y, p.y, a1);
                a2 = fmaf(w.z, p.z, a2); a3 = fmaf(w.w, p.w, a3);
                c0 = fmaf(w.x, q.x, c0); c1 = fmaf(w.y, q.y, c1);
                c2 = fmaf(w.z, q.z, c2); c3 = fmaf(w.w, q.w, c3);
            }
            ghs[tid]             = (a0 + a1) + (a2 + a3) + breg;
            ghs[GH_STRIDE + tid] = (c0 + c1) + (c2 + c3) + breg;
        }
        if (pf) xts[((t + 1) & 1) * 2 + (tid - 408)] = xn;
        __syncthreads();

        // ---- Phase B: gates + state update + outputs (threads 0..255) ----
        if (tid < 256) {
            const int u = tid & 127;
            const int b = tid >> 7;
            const float* gh = ghs + b * GH_STRIDE;
            float xh  = gh[G3];                         // x_hat = h·Wfc + bfc
            float xt  = xts[(t & 1) * 2 + b];
            float cur = (t == 0) ? xt : ((xt == 128.0f) ? xh : xt);

            float gr  = fmaf(cur, wihs[u],       bihs[u])       + gh[u];
            float gz  = fmaf(cur, wihs[u + 128], bihs[u + 128]) + gh[u + 128];
            float gni = fmaf(cur, wihs[u + 256], bihs[u + 256]);

            float r = 1.0f / (1.0f + expf(-gr));
            float z = 1.0f / (1.0f + expf(-gz));
            float n = tanhf(fmaf(r, gh[u + 256], gni));

            float hold = hs[b * HID + u];
            float hnew = fmaf(z, hold - n, n);          // (1-z)*n + z*h
            hs[b * HID + u] = hnew;

            if (u == 0) {
                newin[t * BATCH + b0 + b] = cur;
                if (t > 0) pred[(b0 + b) * (T_STEPS - 1) + (t - 1)] = xh;
            }
        }
        __syncthreads();
    }
}

extern "C" void kernel_launch(void* const* d_in, const int* in_sizes, int n_in,
                              void* d_out, int out_size)
{
    (void)in_sizes; (void)n_in; (void)out_size;
    const float* x    = (const float*)d_in[0];
    const float* Wih  = (const float*)d_in[1];
    const float* Whh  = (const float*)d_in[2];
    const float* bih  = (const float*)d_in[3];
    const float* bhh  = (const float*)d_in[4];
    const float* Wfc  = (const float*)d_in[5];
    const float* bfc  = (const float*)d_in[6];
    float* out = (float*)d_out;

    const size_t smem = (size_t)(NROWS * RPAD + 2 * GH_STRIDE + 2 * HID + 2 * G3 + 4) * sizeof(float);
    cudaFuncSetAttribute(gru_impute_kernel, cudaFuncAttributeMaxDynamicSharedMemorySize, (int)smem);

    gru_impute_kernel<<<BATCH / 2, NTHREADS, smem>>>(x, Wih, Whh, bih, bhh, Wfc, bfc, out);
}

// round 4
// speedup vs baseline: 1.3250x; 1.3250x over previous
#include <cuda_runtime.h>

#define T_STEPS 2048
#define BATCH   256
#define HID     128
#define G3      384
#define NROWS   385      // 384 Whh rows + 1 Wfc row
#define WPAD    68       // smem row stride (floats): 272B = 17*16B -> conflict-free LDS.128
#define NTHREADS 416     // 13 warps
#define GH_STRIDE 400

typedef unsigned long long u64;

__device__ __forceinline__ u64 ffma2(u64 a, u64 b, u64 c) {
    u64 d;
    asm("fma.rn.f32x2 %0, %1, %2, %3;" : "=l"(d) : "l"(a), "l"(b), "l"(c));
    return d;
}
__device__ __forceinline__ float hsum2(u64 v) {
    float x, y;
    asm("mov.b64 {%0, %1}, %2;" : "=f"(x), "=f"(y) : "l"(v));
    return x + y;
}

__global__ void __launch_bounds__(NTHREADS, 1)
gru_impute_kernel(const float* __restrict__ x,     // [B, T] (I=1)
                  const float* __restrict__ Wih,   // [384, 1]
                  const float* __restrict__ Whh,   // [384, 128]
                  const float* __restrict__ bih,   // [384]
                  const float* __restrict__ bhh,   // [384]
                  const float* __restrict__ Wfc,   // [1, 128]
                  const float* __restrict__ bfc,   // [1]
                  float* __restrict__ out)
{
    extern __shared__ float sm[];
    float* ws2 = sm;                        // NROWS * WPAD  (k=64..127 of each row)
    float* ghs = ws2 + NROWS * WPAD;        // 2 * GH_STRIDE
    float* hs  = ghs + 2 * GH_STRIDE;       // 2 * HID  (16B aligned)
    float* xts = hs  + 2 * HID;             // 2 buffers * 2 batches

    const int tid = threadIdx.x;
    const int b0  = blockIdx.x * 2;

    // ---- one-time staging ----
    // smem: second half (k=64..127) of every row
    for (int idx = tid; idx < NROWS * 64; idx += NTHREADS) {
        int r = idx >> 6, c = idx & 63;
        ws2[r * WPAD + c] = (r < G3) ? Whh[r * HID + 64 + c] : Wfc[64 + c];
    }
    for (int idx = tid; idx < 2 * HID; idx += NTHREADS) hs[idx] = 0.0f;
    if (tid < 2) xts[tid] = x[(b0 + tid) * T_STEPS + 0];

    // registers: first half (k=0..63) of this thread's row, as 32 packed pairs
    u64 wr[32];
    if (tid < G3) {
        const u64* wrow = reinterpret_cast<const u64*>(Whh + tid * HID);
        #pragma unroll
        for (int i = 0; i < 32; ++i) wr[i] = __ldg(wrow + i);
    } else if (tid == G3) {
        const u64* wrow = reinterpret_cast<const u64*>(Wfc);
        #pragma unroll
        for (int i = 0; i < 32; ++i) wr[i] = __ldg(wrow + i);
    } else {
        #pragma unroll
        for (int i = 0; i < 32; ++i) wr[i] = 0ull;
    }

    float breg = 0.0f;
    if (tid < G3)       breg = bhh[tid];
    else if (tid == G3) breg = bfc[0];

    // phase-B constants in registers
    float wih_r = 0.f, wih_z = 0.f, wih_n = 0.f, bih_r = 0.f, bih_z = 0.f, bih_n = 0.f;
    if (tid < 256) {
        int u = tid & 127;
        wih_r = Wih[u];        bih_r = bih[u];
        wih_z = Wih[u + 128];  bih_z = bih[u + 128];
        wih_n = Wih[u + 256];  bih_n = bih[u + 256];
    }
    __syncthreads();

    float* newin = out;                       // [T, B]
    float* pred  = out + T_STEPS * BATCH;     // [B, T-1]

    for (int t = 0; t < T_STEPS; ++t) {
        // prefetch x[t+1] on phase-A-idle lanes
        float xn = 0.0f;
        const bool pf = (tid >= 408) && (tid < 410) && (t + 1 < T_STEPS);
        if (pf) xn = x[(b0 + (tid - 408)) * T_STEPS + (t + 1)];

        // ---- Phase A: gh[j][b] = dot(h[b], row_j) + bias ----
        if (tid < NROWS) {
            const ulonglong2* hp0 = reinterpret_cast<const ulonglong2*>(hs);
            const ulonglong2* hp1 = reinterpret_cast<const ulonglong2*>(hs + HID);
            const ulonglong2* wp  = reinterpret_cast<const ulonglong2*>(ws2 + tid * WPAD);
            u64 a0 = 0ull, a1 = 0ull, c0 = 0ull, c1 = 0ull;
            #pragma unroll
            for (int j = 0; j < 16; ++j) {            // k = 0..63 from registers
                ulonglong2 h0 = hp0[j], h1 = hp1[j];
                a0 = ffma2(wr[2 * j],     h0.x, a0);
                a1 = ffma2(wr[2 * j + 1], h0.y, a1);
                c0 = ffma2(wr[2 * j],     h1.x, c0);
                c1 = ffma2(wr[2 * j + 1], h1.y, c1);
            }
            #pragma unroll
            for (int j = 0; j < 16; ++j) {            // k = 64..127 from smem
                ulonglong2 w  = wp[j];
                ulonglong2 h0 = hp0[16 + j], h1 = hp1[16 + j];
                a0 = ffma2(w.x, h0.x, a0);
                a1 = ffma2(w.y, h0.y, a1);
                c0 = ffma2(w.x, h1.x, c0);
                c1 = ffma2(w.y, h1.y, c1);
            }
            ghs[tid]             = hsum2(a0) + hsum2(a1) + breg;
            ghs[GH_STRIDE + tid] = hsum2(c0) + hsum2(c1) + breg;
        }
        if (pf) xts[((t + 1) & 1) * 2 + (tid - 408)] = xn;
        __syncthreads();

        // ---- Phase B: gates + state update + outputs ----
        if (tid < 256) {
            const int u = tid & 127;
            const int b = tid >> 7;
            const float* gh = ghs + b * GH_STRIDE;
            float xh  = gh[G3];
            float xt  = xts[(t & 1) * 2 + b];
            float cur = (t == 0) ? xt : ((xt == 128.0f) ? xh : xt);

            float gr = fmaf(cur, wih_r, bih_r) + gh[u];
            float gz = fmaf(cur, wih_z, bih_z) + gh[u + 128];
            float gn = fmaf(cur, wih_n, bih_n);

            float r = __fdividef(1.0f, 1.0f + __expf(-gr));
            float z = __fdividef(1.0f, 1.0f + __expf(-gz));
            float narg = fmaf(r, gh[u + 256], gn);
            float e2 = __expf(2.0f * narg);
            float n  = 1.0f - __fdividef(2.0f, e2 + 1.0f);   // tanh(narg), saturates correctly

            float hold = hs[b * HID + u];
            float hnew = fmaf(z, hold - n, n);
            hs[b * HID + u] = hnew;

            if (u == 0) {
                newin[t * BATCH + b0 + b] = cur;
                if (t > 0) pred[(b0 + b) * (T_STEPS - 1) + (t - 1)] = xh;
            }
        }
        __syncthreads();
    }
}

extern "C" void kernel_launch(void* const* d_in, const int* in_sizes, int n_in,
                              void* d_out, int out_size)
{
    (void)in_sizes; (void)n_in; (void)out_size;
    const float* x    = (const float*)d_in[0];
    const float* Wih  = (const float*)d_in[1];
    const float* Whh  = (const float*)d_in[2];
    const float* bih  = (const float*)d_in[3];
    const float* bhh  = (const float*)d_in[4];
    const float* Wfc  = (const float*)d_in[5];
    const float* bfc  = (const float*)d_in[6];
    float* out = (float*)d_out;

    const size_t smem = (size_t)(NROWS * WPAD + 2 * GH_STRIDE + 2 * HID + 4) * sizeof(float);
    cudaFuncSetAttribute(gru_impute_kernel, cudaFuncAttributeMaxDynamicSharedMemorySize, (int)smem);

    gru_impute_kernel<<<BATCH / 2, NTHREADS, smem>>>(x, Wih, Whh, bih, bhh, Wfc, bfc, out);
}